// round 14
// baseline (speedup 1.0000x reference)
#include <cuda_runtime.h>
#include <cuda_fp16.h>
#include <cstdint>

#define EMBED  1024
#define HEADS  16
#define HDIM   64
#define NBATCH 2
#define SEQ    2048
#define NROWS  (NBATCH * SEQ)   // 4096
#define ESQ    (EMBED * EMBED)
#define XSZ    (NROWS * EMBED)

// Scratch (no allocation allowed).
__device__ float  g_q[XSZ];
__device__ float  g_v[XSZ];
__device__ __half g_khi[XSZ];
__device__ __half g_vthi[NBATCH * HEADS * HDIM * SEQ];
__device__ __half g_vtlo[NBATCH * HEADS * HDIM * SEQ];
// Input splits: slots 0=values, 1=keys, 2=queries.
__device__ __half g_xhi[3 * XSZ];
__device__ __half g_xlo[3 * XSZ];
// Weight splits: slots 0=W_v, 1=W_k, 2=W_q, 3=W_o.
__device__ __half g_whi[4 * ESQ];
__device__ __half g_wlo[4 * ESQ];
// Flash output split (A operand of the O projection).
__device__ __half g_ahi[XSZ];
__device__ __half g_alo[XSZ];

#define CP_ASYNC16(dst_u32, src_ptr) \
    asm volatile("cp.async.cg.shared.global [%0], [%1], 16;" :: "r"(dst_u32), "l"(src_ptr))

__device__ __forceinline__ void split2(float x, __half& hi, __half& lo) {
    hi = __float2half_rn(x);
    lo = __float2half_rn(x - __half2float(hi));
}
__device__ __forceinline__ uint32_t h2pack(__half a, __half b) {
    __half2 h = __halves2half2(a, b);
    return *(uint32_t*)&h;
}
__device__ __forceinline__ void mma16816(float* c, const uint32_t* a, const uint32_t* b) {
    asm volatile(
        "mma.sync.aligned.m16n8k16.row.col.f32.f16.f16.f32 "
        "{%0,%1,%2,%3}, {%4,%5,%6,%7}, {%8,%9}, {%0,%1,%2,%3};"
        : "+f"(c[0]), "+f"(c[1]), "+f"(c[2]), "+f"(c[3])
        : "r"(a[0]), "r"(a[1]), "r"(a[2]), "r"(a[3]), "r"(b[0]), "r"(b[1]));
}
__device__ __forceinline__ void ldsm_x4(uint32_t& r0, uint32_t& r1,
                                        uint32_t& r2, uint32_t& r3, uint32_t addr) {
    asm volatile("ldmatrix.sync.aligned.m8n8.x4.shared.b16 {%0,%1,%2,%3}, [%4];"
                 : "=r"(r0), "=r"(r1), "=r"(r2), "=r"(r3) : "r"(addr));
}
__device__ __forceinline__ uint32_t packf2(float x, float y) {
    __half2 h = __floats2half2_rn(x, y);
    return *(uint32_t*)&h;
}
__device__ __forceinline__ uint32_t packlo(float x, float y, uint32_t hi) {
    __half2 h = *(__half2*)&hi;
    return packf2(x - __low2float(h), y - __high2float(h));
}

// ---------------------------------------------------------------------------
// Batched splits, 4x float4 per thread (MLP=4).
// ---------------------------------------------------------------------------
__global__ __launch_bounds__(256) void splitx_kernel(
    const float* __restrict__ values, const float* __restrict__ keys,
    const float* __restrict__ queries)
{
    const int slot = blockIdx.y;
    const float* src = (slot == 0) ? values : (slot == 1) ? keys : queries;
    __half* hi = g_xhi + (size_t)slot * XSZ;
    __half* lo = g_xlo + (size_t)slot * XSZ;
    size_t base = (size_t)blockIdx.x * 4096 + threadIdx.x * 4;
    float4 x[4];
#pragma unroll
    for (int j = 0; j < 4; j++) x[j] = *(const float4*)(src + base + j * 1024);
#pragma unroll
    for (int j = 0; j < 4; j++) {
        size_t i = base + j * 1024;
        __half h0,l0,h1,l1,h2,l2,h3,l3;
        split2(x[j].x,h0,l0); split2(x[j].y,h1,l1);
        split2(x[j].z,h2,l2); split2(x[j].w,h3,l3);
        *(uint2*)(hi + i) = make_uint2(h2pack(h0,h1), h2pack(h2,h3));
        *(uint2*)(lo + i) = make_uint2(h2pack(l0,l1), h2pack(l2,l3));
    }
}

__global__ __launch_bounds__(256) void splitw_kernel(
    const float* __restrict__ Wv, const float* __restrict__ Wk,
    const float* __restrict__ Wq, const float* __restrict__ Wo)
{
    const int slot = blockIdx.y;
    const float* src = (slot == 0) ? Wv : (slot == 1) ? Wk : (slot == 2) ? Wq : Wo;
    __half* hi = g_whi + (size_t)slot * ESQ;
    __half* lo = g_wlo + (size_t)slot * ESQ;
    size_t base = (size_t)blockIdx.x * 4096 + threadIdx.x * 4;
    float4 x[4];
#pragma unroll
    for (int j = 0; j < 4; j++) x[j] = *(const float4*)(src + base + j * 1024);
#pragma unroll
    for (int j = 0; j < 4; j++) {
        size_t i = base + j * 1024;
        __half h0,l0,h1,l1,h2,l2,h3,l3;
        split2(x[j].x,h0,l0); split2(x[j].y,h1,l1);
        split2(x[j].z,h2,l2); split2(x[j].w,h3,l3);
        *(uint2*)(hi + i) = make_uint2(h2pack(h0,h1), h2pack(h2,h3));
        *(uint2*)(lo + i) = make_uint2(h2pack(l0,l1), h2pack(l2,l3));
    }
}

// ---------------------------------------------------------------------------
// fp16-split 3-MMA GEMM (NT) — proven R9/R11 shape.
// K projection (z==1) now writes hi-only (flash no longer reads K_lo).
// ---------------------------------------------------------------------------
#define GARR   (128 * 32)
#define GSTAGE (4 * GARR)
#define GEMM16_SMEM (2 * GSTAGE * 2)  // 65536

__device__ __forceinline__ int gswz(int r, int kc) {
    int sr = r >> 1;
    int c  = ((r & 1) << 5) | kc;
    return sr * 64 + ((((c >> 3) ^ (sr & 7)) << 3) | (c & 7));
}

__global__ __launch_bounds__(128) void gemm16_kernel(
    const float* __restrict__ bq, const float* __restrict__ bk,
    const float* __restrict__ bv, float* __restrict__ out_ext, int mode)
{
    extern __shared__ __half gsm[];
    const int z = (mode == 0) ? (int)blockIdx.z : 3;   // 0=Q 1=K 2=V 3=O
    const int wslot = (z == 0) ? 2 : (z == 1) ? 1 : (z == 2) ? 0 : 3;

    const __half *Ahi_g, *Alo_g;
    const float* bias;
    if (z < 3) {
        const int xslot = (z == 0) ? 2 : (z == 1) ? 1 : 0;
        Ahi_g = g_xhi + (size_t)xslot * XSZ;
        Alo_g = g_xlo + (size_t)xslot * XSZ;
        bias  = (z == 0) ? bq : (z == 1) ? bk : bv;
    } else {
        Ahi_g = g_ahi;
        Alo_g = g_alo;
        bias  = bq;              // O launch passes b_o here
    }
    const __half* Bhi_g = g_whi + (size_t)wslot * ESQ;
    const __half* Blo_g = g_wlo + (size_t)wslot * ESQ;

    const int t    = threadIdx.x;
    const int lane = t & 31;
    const int wid  = t >> 5;
    const int g    = lane >> 2;
    const int tg   = lane & 3;
    const int sub  = lane >> 3;
    const int lr   = lane & 7;
    const int wm   = (wid & 1) * 64;
    const int wn   = (wid >> 1) * 64;
    const int c0 = blockIdx.x * 128;
    const int r0 = blockIdx.y * 128;

    const uint32_t smem_u32 = (uint32_t)__cvta_generic_to_shared(gsm);

    float acc[4][8][4];
#pragma unroll
    for (int mi = 0; mi < 4; mi++)
#pragma unroll
        for (int ni = 0; ni < 8; ni++)
#pragma unroll
            for (int e = 0; e < 4; e++) acc[mi][ni][e] = 0.f;

    auto issue = [&](int buf, int k0) {
#pragma unroll
        for (int i = 0; i < 4; i++) {
            int gid = t + i * 128;
            int row = gid >> 2;
            int ch  = gid & 3;
            uint32_t dst = smem_u32 + (uint32_t)(buf * GSTAGE + gswz(row, ch * 8)) * 2;
            size_t aoff = (size_t)(r0 + row) * EMBED + k0 + ch * 8;
            size_t boff = (size_t)(c0 + row) * EMBED + k0 + ch * 8;
            CP_ASYNC16(dst,                Ahi_g + aoff);
            CP_ASYNC16(dst + GARR * 2,     Alo_g + aoff);
            CP_ASYNC16(dst + 2 * GARR * 2, Bhi_g + boff);
            CP_ASYNC16(dst + 3 * GARR * 2, Blo_g + boff);
        }
        asm volatile("cp.async.commit_group;");
    };

    issue(0, 0);

    const int NT = EMBED / 32;
    for (int it = 0; it < NT; it++) {
        if (it + 1 < NT) {
            issue((it + 1) & 1, (it + 1) * 32);
            asm volatile("cp.async.wait_group 1;");
        } else {
            asm volatile("cp.async.wait_group 0;");
        }
        __syncthreads();

        const uint32_t base = (uint32_t)((it & 1) * GSTAGE);
        const uint32_t aho = base, alo_ = base + GARR;
        const uint32_t bho = base + 2 * GARR, blo_ = base + 3 * GARR;

#pragma unroll
        for (int ks = 0; ks < 2; ks++) {
            const int kc0 = ks * 16;
            uint32_t bh[8][2], bl[8][2];
#pragma unroll
            for (int fp = 0; fp < 4; fp++) {
                int row = wn + 8 * (2 * fp + (sub >> 1)) + lr;
                int ch  = kc0 + (sub & 1) * 8;
                uint32_t off = (uint32_t)gswz(row, ch);
                ldsm_x4(bh[2*fp][0], bh[2*fp][1], bh[2*fp+1][0], bh[2*fp+1][1],
                        smem_u32 + (bho + off) * 2);
                ldsm_x4(bl[2*fp][0], bl[2*fp][1], bl[2*fp+1][0], bl[2*fp+1][1],
                        smem_u32 + (blo_ + off) * 2);
            }
#pragma unroll
            for (int mi = 0; mi < 4; mi++) {
                int row = wm + mi * 16 + (sub & 1) * 8 + lr;
                int ch  = kc0 + (sub >> 1) * 8;
                uint32_t off = (uint32_t)gswz(row, ch);
                uint32_t ah[4], al[4];
                ldsm_x4(ah[0], ah[1], ah[2], ah[3], smem_u32 + (aho + off) * 2);
                ldsm_x4(al[0], al[1], al[2], al[3], smem_u32 + (alo_ + off) * 2);
#pragma unroll
                for (int ni = 0; ni < 8; ni++) mma16816(acc[mi][ni], ah, bh[ni]);
#pragma unroll
                for (int ni = 0; ni < 8; ni++) mma16816(acc[mi][ni], ah, bl[ni]);
#pragma unroll
                for (int ni = 0; ni < 8; ni++) mma16816(acc[mi][ni], al, bh[ni]);
            }
        }
        __syncthreads();
    }

    if (z == 1) {
        // K projection: hi-only (flash drops K_lo).
#pragma unroll
        for (int mi = 0; mi < 4; mi++) {
            int r = r0 + wm + mi * 16 + g;
#pragma unroll
            for (int ni = 0; ni < 8; ni++) {
                int cc = c0 + wn + ni * 8 + 2 * tg;
                float bx = bias[cc], by = bias[cc + 1];
                __half h0 = __float2half_rn(acc[mi][ni][0] + bx);
                __half h1 = __float2half_rn(acc[mi][ni][1] + by);
                __half h2 = __float2half_rn(acc[mi][ni][2] + bx);
                __half h3 = __float2half_rn(acc[mi][ni][3] + by);
                *(uint32_t*)(g_khi + (size_t)r * EMBED + cc)     = h2pack(h0,h1);
                *(uint32_t*)(g_khi + (size_t)(r+8) * EMBED + cc) = h2pack(h2,h3);
            }
        }
    } else {
        float* out = (z == 0) ? g_q : (z == 2) ? g_v : out_ext;
#pragma unroll
        for (int mi = 0; mi < 4; mi++) {
            int r = r0 + wm + mi * 16 + g;
#pragma unroll
            for (int ni = 0; ni < 8; ni++) {
                int cc = c0 + wn + ni * 8 + 2 * tg;
                float bx = bias[cc], by = bias[cc + 1];
                *(float2*)(out + (size_t)r * EMBED + cc) =
                    make_float2(acc[mi][ni][0] + bx, acc[mi][ni][1] + by);
                *(float2*)(out + (size_t)(r + 8) * EMBED + cc) =
                    make_float2(acc[mi][ni][2] + bx, acc[mi][ni][3] + by);
            }
        }
    }
}

// ---------------------------------------------------------------------------
// V transpose/split for flash.
// ---------------------------------------------------------------------------
__global__ __launch_bounds__(256) void splitvt_kernel() {
    __shared__ float tile[64][65];
    const int n = blockIdx.z, h = blockIdx.y, s0 = blockIdx.x * 64;
    const int t = threadIdx.x;
#pragma unroll
    for (int i = 0; i < 4; i++) {
        int fi = t + i * 256;
        int r  = fi >> 4;
        int c4 = fi & 15;
        float4 v = *(const float4*)(g_v + ((size_t)n * SEQ + s0 + r) * EMBED + h * HDIM + c4 * 4);
        tile[r][c4 * 4 + 0] = v.x; tile[r][c4 * 4 + 1] = v.y;
        tile[r][c4 * 4 + 2] = v.z; tile[r][c4 * 4 + 3] = v.w;
    }
    __syncthreads();
#pragma unroll
    for (int i = 0; i < 4; i++) {
        int fi = t + i * 256;
        int d   = fi >> 4;
        int sc4 = fi & 15;
        size_t base = ((size_t)(n * HEADS + h) * HDIM + d) * SEQ + s0 + sc4 * 4;
        __half hh[4], ll[4];
#pragma unroll
        for (int j = 0; j < 4; j++) split2(tile[sc4 * 4 + j][d], hh[j], ll[j]);
        *(uint2*)(g_vthi + base) = make_uint2(h2pack(hh[0], hh[1]), h2pack(hh[2], hh[3]));
        *(uint2*)(g_vtlo + base) = make_uint2(h2pack(ll[0], ll[1]), h2pack(ll[2], ll[3]));
    }
}

// ---------------------------------------------------------------------------
// Tensor-core flash attention: 64-row Q tiles, 4 warps.
// QK^T = (Q_hi + Q_lo) * K_hi  (2 MMA terms; K_lo dropped — error ~3e-4).
// PV   = P_hi * (V_hi + V_lo)  (2 MMA terms; P_lo dropped — validated R10).
// Stage arrays: Khi, Vthi, Vtlo (24 KB/stage, 48 KB total).
// ---------------------------------------------------------------------------
#define FT  4096
#define FSTAGE (3 * FT)
#define FLASH16_SMEM (2 * FSTAGE * 2)   // 49152 B

__device__ __forceinline__ int swzh(int r, int c) {
    return (r << 6) + ((((c >> 3) ^ (r & 7)) << 3) | (c & 7));
}

__global__ __launch_bounds__(128) void flash16_kernel() {
    extern __shared__ __half fsm[];
    const int n  = blockIdx.z;
    const int h  = blockIdx.y;
    const int q0 = blockIdx.x * 64;
    const int t    = threadIdx.x;
    const int lane = t & 31;
    const int wid  = t >> 5;
    const int g    = lane >> 2;
    const int tg   = lane & 3;
    const int sub  = lane >> 3;
    const int lr   = lane & 7;
    const int wm   = wid * 16;

    const uint32_t smem_u32 = (uint32_t)__cvta_generic_to_shared(fsm);

    uint32_t qa_h[4][4], qa_l[4][4];
    {
        const float* Qg = g_q + ((size_t)n * SEQ + q0 + wm) * EMBED + h * HDIM;
#pragma unroll
        for (int s = 0; s < 4; s++) {
            int c0 = 16 * s + 2 * tg;
#pragma unroll
            for (int rr = 0; rr < 2; rr++) {
                int row = g + rr * 8;
                float2 q01 = *(const float2*)(Qg + (size_t)row * EMBED + c0);
                float2 q23 = *(const float2*)(Qg + (size_t)row * EMBED + c0 + 8);
                q01.x *= 0.125f; q01.y *= 0.125f;
                q23.x *= 0.125f; q23.y *= 0.125f;
                qa_h[s][rr]     = packf2(q01.x, q01.y);
                qa_l[s][rr]     = packlo(q01.x, q01.y, qa_h[s][rr]);
                qa_h[s][rr + 2] = packf2(q23.x, q23.y);
                qa_l[s][rr + 2] = packlo(q23.x, q23.y, qa_h[s][rr + 2]);
            }
        }
    }

    float oacc[8][4];
#pragma unroll
    for (int nf = 0; nf < 8; nf++)
#pragma unroll
        for (int e = 0; e < 4; e++) oacc[nf][e] = 0.f;
    float m0 = -1e30f, m1 = -1e30f, l0 = 0.f, l1 = 0.f;

    const __half* srcK_hi = g_khi + ((size_t)n * SEQ) * EMBED + h * HDIM;
    const __half* srcV_hi = g_vthi + (size_t)(n * HEADS + h) * HDIM * SEQ;
    const __half* srcV_lo = g_vtlo + (size_t)(n * HEADS + h) * HDIM * SEQ;

    auto issue = [&](int tileidx, int buf) {
        int s0 = tileidx * 64;
#pragma unroll
        for (int i = 0; i < 4; i++) {
            int gid = t + i * 128;
            int r = gid >> 3;
            int c = gid & 7;
            uint32_t dsth = (uint32_t)(buf * FSTAGE + r * 64 + ((c ^ (r & 7)) << 3));
            CP_ASYNC16(smem_u32 + (dsth) * 2,
                       srcK_hi + (size_t)(s0 + r) * EMBED + c * 8);
            CP_ASYNC16(smem_u32 + (dsth + FT) * 2,
                       srcV_hi + (size_t)r * SEQ + s0 + c * 8);
            CP_ASYNC16(smem_u32 + (dsth + 2 * FT) * 2,
                       srcV_lo + (size_t)r * SEQ + s0 + c * 8);
        }
        asm volatile("cp.async.commit_group;");
    };

    issue(0, 0);

    const int NT = SEQ / 64;
    for (int it = 0; it < NT; it++) {
        if (it + 1 < NT) {
            issue(it + 1, (it + 1) & 1);
            asm volatile("cp.async.wait_group 1;");
        } else {
            asm volatile("cp.async.wait_group 0;");
        }
        __syncthreads();

        const uint32_t kho = (uint32_t)((it & 1) * FSTAGE);
        const uint32_t vho = kho + FT;
        const uint32_t vlo_ = kho + 2 * FT;

        float sa[8][4];
#pragma unroll
        for (int nf = 0; nf < 8; nf++)
#pragma unroll
            for (int e = 0; e < 4; e++) sa[nf][e] = 0.f;

#pragma unroll
        for (int s = 0; s < 4; s++) {
            uint32_t bh[8][2];
#pragma unroll
            for (int fp = 0; fp < 4; fp++) {
                int row = 8 * (2 * fp + (sub >> 1)) + lr;
                int ch  = 16 * s + (sub & 1) * 8;
                uint32_t off = (uint32_t)swzh(row, ch);
                ldsm_x4(bh[2*fp][0], bh[2*fp][1], bh[2*fp+1][0], bh[2*fp+1][1],
                        smem_u32 + (kho + off) * 2);
            }
#pragma unroll
            for (int j = 0; j < 8; j++) mma16816(sa[j], qa_h[s], bh[j]);
#pragma unroll
            for (int j = 0; j < 8; j++) mma16816(sa[j], qa_l[s], bh[j]);
        }

        float mx0 = -1e30f, mx1 = -1e30f;
#pragma unroll
        for (int nf = 0; nf < 8; nf++) {
            mx0 = fmaxf(mx0, fmaxf(sa[nf][0], sa[nf][1]));
            mx1 = fmaxf(mx1, fmaxf(sa[nf][2], sa[nf][3]));
        }
        mx0 = fmaxf(mx0, __shfl_xor_sync(0xffffffffu, mx0, 1));
        mx0 = fmaxf(mx0, __shfl_xor_sync(0xffffffffu, mx0, 2));
        mx1 = fmaxf(mx1, __shfl_xor_sync(0xffffffffu, mx1, 1));
        mx1 = fmaxf(mx1, __shfl_xor_sync(0xffffffffu, mx1, 2));
        float mn0 = fmaxf(m0, mx0), mn1 = fmaxf(m1, mx1);
        float corr0 = __expf(m0 - mn0), corr1 = __expf(m1 - mn1);
        m0 = mn0; m1 = mn1;
        float rs0 = 0.f, rs1 = 0.f;
#pragma unroll
        for (int nf = 0; nf < 8; nf++) {
            sa[nf][0] = __expf(sa[nf][0] - mn0); rs0 += sa[nf][0];
            sa[nf][1] = __expf(sa[nf][1] - mn0); rs0 += sa[nf][1];
            sa[nf][2] = __expf(sa[nf][2] - mn1); rs1 += sa[nf][2];
            sa[nf][3] = __expf(sa[nf][3] - mn1); rs1 += sa[nf][3];
        }
        rs0 += __shfl_xor_sync(0xffffffffu, rs0, 1);
        rs0 += __shfl_xor_sync(0xffffffffu, rs0, 2);
        rs1 += __shfl_xor_sync(0xffffffffu, rs1, 1);
        rs1 += __shfl_xor_sync(0xffffffffu, rs1, 2);
        l0 = l0 * corr0 + rs0;
        l1 = l1 * corr1 + rs1;
#pragma unroll
        for (int nf = 0; nf < 8; nf++) {
            oacc[nf][0] *= corr0; oacc[nf][1] *= corr0;
            oacc[nf][2] *= corr1; oacc[nf][3] *= corr1;
        }

        uint32_t pa_h[4][4];
#pragma unroll
        for (int sp = 0; sp < 4; sp++) {
            pa_h[sp][0] = packf2(sa[2 * sp][0], sa[2 * sp][1]);
            pa_h[sp][1] = packf2(sa[2 * sp][2], sa[2 * sp][3]);
            pa_h[sp][2] = packf2(sa[2 * sp + 1][0], sa[2 * sp + 1][1]);
            pa_h[sp][3] = packf2(sa[2 * sp + 1][2], sa[2 * sp + 1][3]);
        }

#pragma unroll
        for (int sp = 0; sp < 4; sp++) {
            uint32_t bh[8][2], bl[8][2];
#pragma unroll
            for (int fp = 0; fp < 4; fp++) {
                int row = 8 * (2 * fp + (sub >> 1)) + lr;
                int ch  = 16 * sp + (sub & 1) * 8;
                uint32_t off = (uint32_t)swzh(row, ch);
                ldsm_x4(bh[2*fp][0], bh[2*fp][1], bh[2*fp+1][0], bh[2*fp+1][1],
                        smem_u32 + (vho + off) * 2);
                ldsm_x4(bl[2*fp][0], bl[2*fp][1], bl[2*fp+1][0], bl[2*fp+1][1],
                        smem_u32 + (vlo_ + off) * 2);
            }
#pragma unroll
            for (int j = 0; j < 8; j++) mma16816(oacc[j], pa_h[sp], bh[j]);
#pragma unroll
            for (int j = 0; j < 8; j++) mma16816(oacc[j], pa_h[sp], bl[j]);
        }
        __syncthreads();
    }

    size_t row0 = (size_t)n * SEQ + q0 + wm + g;
    int colb = h * HDIM;
    float inv0 = 1.0f / l0, inv1 = 1.0f / l1;
#pragma unroll
    for (int nf = 0; nf < 8; nf++) {
        int cc = colb + 8 * nf + 2 * tg;
        float z0 = oacc[nf][0] * inv0, z1 = oacc[nf][1] * inv0;
        float z2 = oacc[nf][2] * inv1, z3 = oacc[nf][3] * inv1;
        __half h0,l0h,h1,l1h,h2,l2h,h3,l3h;
        split2(z0,h0,l0h); split2(z1,h1,l1h);
        split2(z2,h2,l2h); split2(z3,h3,l3h);
        *(uint32_t*)(g_ahi + row0 * EMBED + cc)       = h2pack(h0,h1);
        *(uint32_t*)(g_alo + row0 * EMBED + cc)       = h2pack(l0h,l1h);
        *(uint32_t*)(g_ahi + (row0 + 8) * EMBED + cc) = h2pack(h2,h3);
        *(uint32_t*)(g_alo + (row0 + 8) * EMBED + cc) = h2pack(l2h,l3h);
    }
}

// ---------------------------------------------------------------------------
// Launch
// ---------------------------------------------------------------------------
extern "C" void kernel_launch(void* const* d_in, const int* in_sizes, int n_in,
                              void* d_out, int out_size)
{
    const float* values  = (const float*)d_in[0];
    const float* keys    = (const float*)d_in[1];
    const float* queries = (const float*)d_in[2];
    const float* W_v = (const float*)d_in[3];
    const float* b_v = (const float*)d_in[4];
    const float* W_k = (const float*)d_in[5];
    const float* b_k = (const float*)d_in[6];
    const float* W_q = (const float*)d_in[7];
    const float* b_q = (const float*)d_in[8];
    const float* W_o = (const float*)d_in[9];
    const float* b_o = (const float*)d_in[10];
    float* out = (float*)d_out;

    cudaFuncSetAttribute(flash16_kernel,
                         cudaFuncAttributeMaxDynamicSharedMemorySize, FLASH16_SMEM);
    cudaFuncSetAttribute(gemm16_kernel,
                         cudaFuncAttributeMaxDynamicSharedMemorySize, GEMM16_SMEM);

    // Batched operand splits.
    splitw_kernel<<<dim3(ESQ / 4096, 4), 256>>>(W_v, W_k, W_q, W_o);
    splitx_kernel<<<dim3(XSZ / 4096, 3), 256>>>(values, keys, queries);

    // Fused Q/K/V projections.
    gemm16_kernel<<<dim3(EMBED / 128, NROWS / 128, 3), 128, GEMM16_SMEM>>>(
        b_q, b_k, b_v, nullptr, 0);

    // V transpose/split + flash.
    splitvt_kernel<<<dim3(SEQ / 64, HEADS, NBATCH), 256>>>();
    flash16_kernel<<<dim3(SEQ / 64, HEADS, NBATCH), 128, FLASH16_SMEM>>>();

    // Output projection.
    gemm16_kernel<<<dim3(EMBED / 128, NROWS / 128, 1), 128, GEMM16_SMEM>>>(
        b_o, nullptr, nullptr, out, 1);
}

// round 15
// speedup vs baseline: 1.6830x; 1.6830x over previous
#include <cuda_runtime.h>
#include <cuda_fp16.h>
#include <cstdint>

#define EMBED  1024
#define HEADS  16
#define HDIM   64
#define NBATCH 2
#define SEQ    2048
#define NROWS  (NBATCH * SEQ)   // 4096
#define ESQ    (EMBED * EMBED)
#define XSZ    (NROWS * EMBED)

// Scratch (no allocation allowed).
__device__ float  g_q[XSZ];
__device__ float  g_v[XSZ];
__device__ __half g_khi[XSZ];
__device__ __half g_klo[XSZ];
__device__ __half g_vthi[NBATCH * HEADS * HDIM * SEQ];
__device__ __half g_vtlo[NBATCH * HEADS * HDIM * SEQ];
// Input splits (hi only — GEMMs are 2-term): slots 0=values, 1=keys, 2=queries.
__device__ __half g_xhi[3 * XSZ];
// Weight splits: slots 0=W_v, 1=W_k, 2=W_q, 3=W_o.
__device__ __half g_whi[4 * ESQ];
__device__ __half g_wlo[4 * ESQ];
// Flash output (hi only; A operand of the O projection).
__device__ __half g_ahi[XSZ];

#define CP_ASYNC16(dst_u32, src_ptr) \
    asm volatile("cp.async.cg.shared.global [%0], [%1], 16;" :: "r"(dst_u32), "l"(src_ptr))

__device__ __forceinline__ void split2(float x, __half& hi, __half& lo) {
    hi = __float2half_rn(x);
    lo = __float2half_rn(x - __half2float(hi));
}
__device__ __forceinline__ uint32_t h2pack(__half a, __half b) {
    __half2 h = __halves2half2(a, b);
    return *(uint32_t*)&h;
}
__device__ __forceinline__ void mma16816(float* c, const uint32_t* a, const uint32_t* b) {
    asm volatile(
        "mma.sync.aligned.m16n8k16.row.col.f32.f16.f16.f32 "
        "{%0,%1,%2,%3}, {%4,%5,%6,%7}, {%8,%9}, {%0,%1,%2,%3};"
        : "+f"(c[0]), "+f"(c[1]), "+f"(c[2]), "+f"(c[3])
        : "r"(a[0]), "r"(a[1]), "r"(a[2]), "r"(a[3]), "r"(b[0]), "r"(b[1]));
}
__device__ __forceinline__ void ldsm_x4(uint32_t& r0, uint32_t& r1,
                                        uint32_t& r2, uint32_t& r3, uint32_t addr) {
    asm volatile("ldmatrix.sync.aligned.m8n8.x4.shared.b16 {%0,%1,%2,%3}, [%4];"
                 : "=r"(r0), "=r"(r1), "=r"(r2), "=r"(r3) : "r"(addr));
}
__device__ __forceinline__ uint32_t packf2(float x, float y) {
    __half2 h = __floats2half2_rn(x, y);
    return *(uint32_t*)&h;
}
__device__ __forceinline__ uint32_t packlo(float x, float y, uint32_t hi) {
    __half2 h = *(__half2*)&hi;
    return packf2(x - __low2float(h), y - __high2float(h));
}

// ---------------------------------------------------------------------------
// Batched splits, 4x float4 per thread (MLP=4).
// splitx: hi only (GEMM A side is 2-term fp16).
// ---------------------------------------------------------------------------
__global__ __launch_bounds__(256) void splitx_kernel(
    const float* __restrict__ values, const float* __restrict__ keys,
    const float* __restrict__ queries)
{
    const int slot = blockIdx.y;
    const float* src = (slot == 0) ? values : (slot == 1) ? keys : queries;
    __half* hi = g_xhi + (size_t)slot * XSZ;
    size_t base = (size_t)blockIdx.x * 4096 + threadIdx.x * 4;
    float4 x[4];
#pragma unroll
    for (int j = 0; j < 4; j++) x[j] = *(const float4*)(src + base + j * 1024);
#pragma unroll
    for (int j = 0; j < 4; j++) {
        size_t i = base + j * 1024;
        __half h0 = __float2half_rn(x[j].x), h1 = __float2half_rn(x[j].y);
        __half h2 = __float2half_rn(x[j].z), h3 = __float2half_rn(x[j].w);
        *(uint2*)(hi + i) = make_uint2(h2pack(h0,h1), h2pack(h2,h3));
    }
}

__global__ __launch_bounds__(256) void splitw_kernel(
    const float* __restrict__ Wv, const float* __restrict__ Wk,
    const float* __restrict__ Wq, const float* __restrict__ Wo)
{
    const int slot = blockIdx.y;
    const float* src = (slot == 0) ? Wv : (slot == 1) ? Wk : (slot == 2) ? Wq : Wo;
    __half* hi = g_whi + (size_t)slot * ESQ;
    __half* lo = g_wlo + (size_t)slot * ESQ;
    size_t base = (size_t)blockIdx.x * 4096 + threadIdx.x * 4;
    float4 x[4];
#pragma unroll
    for (int j = 0; j < 4; j++) x[j] = *(const float4*)(src + base + j * 1024);
#pragma unroll
    for (int j = 0; j < 4; j++) {
        size_t i = base + j * 1024;
        __half h0,l0,h1,l1,h2,l2,h3,l3;
        split2(x[j].x,h0,l0); split2(x[j].y,h1,l1);
        split2(x[j].z,h2,l2); split2(x[j].w,h3,l3);
        *(uint2*)(hi + i) = make_uint2(h2pack(h0,h1), h2pack(h2,h3));
        *(uint2*)(lo + i) = make_uint2(h2pack(l0,l1), h2pack(l2,l3));
    }
}

// ---------------------------------------------------------------------------
// fp16 2-term GEMM (NT): out = A_hi*(W_hi + W_lo) + b. A side fp16-rounded.
// Block 128x128, BK=32, 128 threads. Arrays: Ahi, Bhi, Blo (48 KB smem).
// ---------------------------------------------------------------------------
#define GARR   (128 * 32)
#define GSTAGE (3 * GARR)
#define GEMM16_SMEM (2 * GSTAGE * 2)  // 49152

__device__ __forceinline__ int gswz(int r, int kc) {
    int sr = r >> 1;
    int c  = ((r & 1) << 5) | kc;
    return sr * 64 + ((((c >> 3) ^ (sr & 7)) << 3) | (c & 7));
}

__global__ __launch_bounds__(128) void gemm16_kernel(
    const float* __restrict__ bq, const float* __restrict__ bk,
    const float* __restrict__ bv, float* __restrict__ out_ext, int mode)
{
    extern __shared__ __half gsm[];
    const int z = (mode == 0) ? (int)blockIdx.z : 3;   // 0=Q 1=K 2=V 3=O
    const int wslot = (z == 0) ? 2 : (z == 1) ? 1 : (z == 2) ? 0 : 3;

    const __half* Ahi_g;
    const float* bias;
    if (z < 3) {
        const int xslot = (z == 0) ? 2 : (z == 1) ? 1 : 0;
        Ahi_g = g_xhi + (size_t)xslot * XSZ;
        bias  = (z == 0) ? bq : (z == 1) ? bk : bv;
    } else {
        Ahi_g = g_ahi;
        bias  = bq;              // O launch passes b_o here
    }
    const __half* Bhi_g = g_whi + (size_t)wslot * ESQ;
    const __half* Blo_g = g_wlo + (size_t)wslot * ESQ;

    const int t    = threadIdx.x;
    const int lane = t & 31;
    const int wid  = t >> 5;
    const int g    = lane >> 2;
    const int tg   = lane & 3;
    const int sub  = lane >> 3;
    const int lr   = lane & 7;
    const int wm   = (wid & 1) * 64;
    const int wn   = (wid >> 1) * 64;
    const int c0 = blockIdx.x * 128;
    const int r0 = blockIdx.y * 128;

    const uint32_t smem_u32 = (uint32_t)__cvta_generic_to_shared(gsm);

    float acc[4][8][4];
#pragma unroll
    for (int mi = 0; mi < 4; mi++)
#pragma unroll
        for (int ni = 0; ni < 8; ni++)
#pragma unroll
            for (int e = 0; e < 4; e++) acc[mi][ni][e] = 0.f;

    auto issue = [&](int buf, int k0) {
#pragma unroll
        for (int i = 0; i < 4; i++) {
            int gid = t + i * 128;
            int row = gid >> 2;
            int ch  = gid & 3;
            uint32_t dst = smem_u32 + (uint32_t)(buf * GSTAGE + gswz(row, ch * 8)) * 2;
            size_t aoff = (size_t)(r0 + row) * EMBED + k0 + ch * 8;
            size_t boff = (size_t)(c0 + row) * EMBED + k0 + ch * 8;
            CP_ASYNC16(dst,                Ahi_g + aoff);
            CP_ASYNC16(dst + GARR * 2,     Bhi_g + boff);
            CP_ASYNC16(dst + 2 * GARR * 2, Blo_g + boff);
        }
        asm volatile("cp.async.commit_group;");
    };

    issue(0, 0);

    const int NT = EMBED / 32;
    for (int it = 0; it < NT; it++) {
        if (it + 1 < NT) {
            issue((it + 1) & 1, (it + 1) * 32);
            asm volatile("cp.async.wait_group 1;");
        } else {
            asm volatile("cp.async.wait_group 0;");
        }
        __syncthreads();

        const uint32_t base = (uint32_t)((it & 1) * GSTAGE);
        const uint32_t aho = base;
        const uint32_t bho = base + GARR, blo_ = base + 2 * GARR;

#pragma unroll
        for (int ks = 0; ks < 2; ks++) {
            const int kc0 = ks * 16;
            uint32_t bh[8][2], bl[8][2];
#pragma unroll
            for (int fp = 0; fp < 4; fp++) {
                int row = wn + 8 * (2 * fp + (sub >> 1)) + lr;
                int ch  = kc0 + (sub & 1) * 8;
                uint32_t off = (uint32_t)gswz(row, ch);
                ldsm_x4(bh[2*fp][0], bh[2*fp][1], bh[2*fp+1][0], bh[2*fp+1][1],
                        smem_u32 + (bho + off) * 2);
                ldsm_x4(bl[2*fp][0], bl[2*fp][1], bl[2*fp+1][0], bl[2*fp+1][1],
                        smem_u32 + (blo_ + off) * 2);
            }
#pragma unroll
            for (int mi = 0; mi < 4; mi++) {
                int row = wm + mi * 16 + (sub & 1) * 8 + lr;
                int ch  = kc0 + (sub >> 1) * 8;
                uint32_t off = (uint32_t)gswz(row, ch);
                uint32_t ah[4];
                ldsm_x4(ah[0], ah[1], ah[2], ah[3], smem_u32 + (aho + off) * 2);
#pragma unroll
                for (int ni = 0; ni < 8; ni++) mma16816(acc[mi][ni], ah, bh[ni]);
#pragma unroll
                for (int ni = 0; ni < 8; ni++) mma16816(acc[mi][ni], ah, bl[ni]);
            }
        }
        __syncthreads();
    }

    if (z == 1) {
        // K projection: write split hi/lo (flash QK uses both).
#pragma unroll
        for (int mi = 0; mi < 4; mi++) {
            int r = r0 + wm + mi * 16 + g;
#pragma unroll
            for (int ni = 0; ni < 8; ni++) {
                int cc = c0 + wn + ni * 8 + 2 * tg;
                float bx = bias[cc], by = bias[cc + 1];
                float z0 = acc[mi][ni][0] + bx, z1 = acc[mi][ni][1] + by;
                float z2 = acc[mi][ni][2] + bx, z3 = acc[mi][ni][3] + by;
                __half h0,l0,h1,l1,h2,l2,h3,l3;
                split2(z0,h0,l0); split2(z1,h1,l1);
                split2(z2,h2,l2); split2(z3,h3,l3);
                *(uint32_t*)(g_khi + (size_t)r * EMBED + cc)     = h2pack(h0,h1);
                *(uint32_t*)(g_klo + (size_t)r * EMBED + cc)     = h2pack(l0,l1);
                *(uint32_t*)(g_khi + (size_t)(r+8) * EMBED + cc) = h2pack(h2,h3);
                *(uint32_t*)(g_klo + (size_t)(r+8) * EMBED + cc) = h2pack(l2,l3);
            }
        }
    } else {
        float* out = (z == 0) ? g_q : (z == 2) ? g_v : out_ext;
#pragma unroll
        for (int mi = 0; mi < 4; mi++) {
            int r = r0 + wm + mi * 16 + g;
#pragma unroll
            for (int ni = 0; ni < 8; ni++) {
                int cc = c0 + wn + ni * 8 + 2 * tg;
                float bx = bias[cc], by = bias[cc + 1];
                *(float2*)(out + (size_t)r * EMBED + cc) =
                    make_float2(acc[mi][ni][0] + bx, acc[mi][ni][1] + by);
                *(float2*)(out + (size_t)(r + 8) * EMBED + cc) =
                    make_float2(acc[mi][ni][2] + bx, acc[mi][ni][3] + by);
            }
        }
    }
}

// ---------------------------------------------------------------------------
// V transpose/split for flash.
// ---------------------------------------------------------------------------
__global__ __launch_bounds__(256) void splitvt_kernel() {
    __shared__ float tile[64][65];
    const int n = blockIdx.z, h = blockIdx.y, s0 = blockIdx.x * 64;
    const int t = threadIdx.x;
#pragma unroll
    for (int i = 0; i < 4; i++) {
        int fi = t + i * 256;
        int r  = fi >> 4;
        int c4 = fi & 15;
        float4 v = *(const float4*)(g_v + ((size_t)n * SEQ + s0 + r) * EMBED + h * HDIM + c4 * 4);
        tile[r][c4 * 4 + 0] = v.x; tile[r][c4 * 4 + 1] = v.y;
        tile[r][c4 * 4 + 2] = v.z; tile[r][c4 * 4 + 3] = v.w;
    }
    __syncthreads();
#pragma unroll
    for (int i = 0; i < 4; i++) {
        int fi = t + i * 256;
        int d   = fi >> 4;
        int sc4 = fi & 15;
        size_t base = ((size_t)(n * HEADS + h) * HDIM + d) * SEQ + s0 + sc4 * 4;
        __half hh[4], ll[4];
#pragma unroll
        for (int j = 0; j < 4; j++) split2(tile[sc4 * 4 + j][d], hh[j], ll[j]);
        *(uint2*)(g_vthi + base) = make_uint2(h2pack(hh[0], hh[1]), h2pack(hh[2], hh[3]));
        *(uint2*)(g_vtlo + base) = make_uint2(h2pack(ll[0], ll[1]), h2pack(ll[2], ll[3]));
    }
}

// ---------------------------------------------------------------------------
// Tensor-core flash attention — R11 mainloop (proven 235 us), epilogue
// writes hi only (O projection is 2-term).
// ---------------------------------------------------------------------------
#define FT  4096
#define FSTAGE (4 * FT)
#define FLASH16_SMEM (2 * FSTAGE * 2)   // 65536 B

__device__ __forceinline__ int swzh(int r, int c) {
    return (r << 6) + ((((c >> 3) ^ (r & 7)) << 3) | (c & 7));
}

__global__ __launch_bounds__(128) void flash16_kernel() {
    extern __shared__ __half fsm[];
    const int n  = blockIdx.z;
    const int h  = blockIdx.y;
    const int q0 = blockIdx.x * 64;
    const int t    = threadIdx.x;
    const int lane = t & 31;
    const int wid  = t >> 5;
    const int g    = lane >> 2;
    const int tg   = lane & 3;
    const int sub  = lane >> 3;
    const int lr   = lane & 7;
    const int wm   = wid * 16;

    const uint32_t smem_u32 = (uint32_t)__cvta_generic_to_shared(fsm);

    uint32_t qa_h[4][4], qa_l[4][4];
    {
        const float* Qg = g_q + ((size_t)n * SEQ + q0 + wm) * EMBED + h * HDIM;
#pragma unroll
        for (int s = 0; s < 4; s++) {
            int c0 = 16 * s + 2 * tg;
#pragma unroll
            for (int rr = 0; rr < 2; rr++) {
                int row = g + rr * 8;
                float2 q01 = *(const float2*)(Qg + (size_t)row * EMBED + c0);
                float2 q23 = *(const float2*)(Qg + (size_t)row * EMBED + c0 + 8);
                q01.x *= 0.125f; q01.y *= 0.125f;
                q23.x *= 0.125f; q23.y *= 0.125f;
                qa_h[s][rr]     = packf2(q01.x, q01.y);
                qa_l[s][rr]     = packlo(q01.x, q01.y, qa_h[s][rr]);
                qa_h[s][rr + 2] = packf2(q23.x, q23.y);
                qa_l[s][rr + 2] = packlo(q23.x, q23.y, qa_h[s][rr + 2]);
            }
        }
    }

    float oacc[8][4];
#pragma unroll
    for (int nf = 0; nf < 8; nf++)
#pragma unroll
        for (int e = 0; e < 4; e++) oacc[nf][e] = 0.f;
    float m0 = -1e30f, m1 = -1e30f, l0 = 0.f, l1 = 0.f;

    const __half* srcK_hi = g_khi + ((size_t)n * SEQ) * EMBED + h * HDIM;
    const __half* srcK_lo = g_klo + ((size_t)n * SEQ) * EMBED + h * HDIM;
    const __half* srcV_hi = g_vthi + (size_t)(n * HEADS + h) * HDIM * SEQ;
    const __half* srcV_lo = g_vtlo + (size_t)(n * HEADS + h) * HDIM * SEQ;

    auto issue = [&](int tileidx, int buf) {
        int s0 = tileidx * 64;
#pragma unroll
        for (int i = 0; i < 4; i++) {
            int gid = t + i * 128;
            int r = gid >> 3;
            int c = gid & 7;
            uint32_t dsth = (uint32_t)(buf * FSTAGE + r * 64 + ((c ^ (r & 7)) << 3));
            CP_ASYNC16(smem_u32 + (dsth) * 2,
                       srcK_hi + (size_t)(s0 + r) * EMBED + c * 8);
            CP_ASYNC16(smem_u32 + (dsth + FT) * 2,
                       srcK_lo + (size_t)(s0 + r) * EMBED + c * 8);
            CP_ASYNC16(smem_u32 + (dsth + 2 * FT) * 2,
                       srcV_hi + (size_t)r * SEQ + s0 + c * 8);
            CP_ASYNC16(smem_u32 + (dsth + 3 * FT) * 2,
                       srcV_lo + (size_t)r * SEQ + s0 + c * 8);
        }
        asm volatile("cp.async.commit_group;");
    };

    issue(0, 0);

    const int NT = SEQ / 64;
    for (int it = 0; it < NT; it++) {
        if (it + 1 < NT) {
            issue(it + 1, (it + 1) & 1);
            asm volatile("cp.async.wait_group 1;");
        } else {
            asm volatile("cp.async.wait_group 0;");
        }
        __syncthreads();

        const uint32_t kho = (uint32_t)((it & 1) * FSTAGE);
        const uint32_t klo_ = kho + FT;
        const uint32_t vho = kho + 2 * FT;
        const uint32_t vlo_ = kho + 3 * FT;

        float sa[8][4];
#pragma unroll
        for (int nf = 0; nf < 8; nf++)
#pragma unroll
            for (int e = 0; e < 4; e++) sa[nf][e] = 0.f;

#pragma unroll
        for (int s = 0; s < 4; s++) {
            uint32_t bh[8][2], bl[8][2];
#pragma unroll
            for (int fp = 0; fp < 4; fp++) {
                int row = 8 * (2 * fp + (sub >> 1)) + lr;
                int ch  = 16 * s + (sub & 1) * 8;
                uint32_t off = (uint32_t)swzh(row, ch);
                ldsm_x4(bh[2*fp][0], bh[2*fp][1], bh[2*fp+1][0], bh[2*fp+1][1],
                        smem_u32 + (kho + off) * 2);
                ldsm_x4(bl[2*fp][0], bl[2*fp][1], bl[2*fp+1][0], bl[2*fp+1][1],
                        smem_u32 + (klo_ + off) * 2);
            }
#pragma unroll
            for (int j = 0; j < 8; j++) mma16816(sa[j], qa_h[s], bh[j]);
#pragma unroll
            for (int j = 0; j < 8; j++) mma16816(sa[j], qa_h[s], bl[j]);
#pragma unroll
            for (int j = 0; j < 8; j++) mma16816(sa[j], qa_l[s], bh[j]);
        }

        float mx0 = -1e30f, mx1 = -1e30f;
#pragma unroll
        for (int nf = 0; nf < 8; nf++) {
            mx0 = fmaxf(mx0, fmaxf(sa[nf][0], sa[nf][1]));
            mx1 = fmaxf(mx1, fmaxf(sa[nf][2], sa[nf][3]));
        }
        mx0 = fmaxf(mx0, __shfl_xor_sync(0xffffffffu, mx0, 1));
        mx0 = fmaxf(mx0, __shfl_xor_sync(0xffffffffu, mx0, 2));
        mx1 = fmaxf(mx1, __shfl_xor_sync(0xffffffffu, mx1, 1));
        mx1 = fmaxf(mx1, __shfl_xor_sync(0xffffffffu, mx1, 2));
        float mn0 = fmaxf(m0, mx0), mn1 = fmaxf(m1, mx1);
        float corr0 = __expf(m0 - mn0), corr1 = __expf(m1 - mn1);
        m0 = mn0; m1 = mn1;
        float rs0 = 0.f, rs1 = 0.f;
#pragma unroll
        for (int nf = 0; nf < 8; nf++) {
            sa[nf][0] = __expf(sa[nf][0] - mn0); rs0 += sa[nf][0];
            sa[nf][1] = __expf(sa[nf][1] - mn0); rs0 += sa[nf][1];
            sa[nf][2] = __expf(sa[nf][2] - mn1); rs1 += sa[nf][2];
            sa[nf][3] = __expf(sa[nf][3] - mn1); rs1 += sa[nf][3];
        }
        rs0 += __shfl_xor_sync(0xffffffffu, rs0, 1);
        rs0 += __shfl_xor_sync(0xffffffffu, rs0, 2);
        rs1 += __shfl_xor_sync(0xffffffffu, rs1, 1);
        rs1 += __shfl_xor_sync(0xffffffffu, rs1, 2);
        l0 = l0 * corr0 + rs0;
        l1 = l1 * corr1 + rs1;
#pragma unroll
        for (int nf = 0; nf < 8; nf++) {
            oacc[nf][0] *= corr0; oacc[nf][1] *= corr0;
            oacc[nf][2] *= corr1; oacc[nf][3] *= corr1;
        }

        uint32_t pa_h[4][4];
#pragma unroll
        for (int sp = 0; sp < 4; sp++) {
            pa_h[sp][0] = packf2(sa[2 * sp][0], sa[2 * sp][1]);
            pa_h[sp][1] = packf2(sa[2 * sp][2], sa[2 * sp][3]);
            pa_h[sp][2] = packf2(sa[2 * sp + 1][0], sa[2 * sp + 1][1]);
            pa_h[sp][3] = packf2(sa[2 * sp + 1][2], sa[2 * sp + 1][3]);
        }

#pragma unroll
        for (int sp = 0; sp < 4; sp++) {
            uint32_t bh[8][2], bl[8][2];
#pragma unroll
            for (int fp = 0; fp < 4; fp++) {
                int row = 8 * (2 * fp + (sub >> 1)) + lr;
                int ch  = 16 * sp + (sub & 1) * 8;
                uint32_t off = (uint32_t)swzh(row, ch);
                ldsm_x4(bh[2*fp][0], bh[2*fp][1], bh[2*fp+1][0], bh[2*fp+1][1],
                        smem_u32 + (vho + off) * 2);
                ldsm_x4(bl[2*fp][0], bl[2*fp][1], bl[2*fp+1][0], bl[2*fp+1][1],
                        smem_u32 + (vlo_ + off) * 2);
            }
#pragma unroll
            for (int j = 0; j < 8; j++) mma16816(oacc[j], pa_h[sp], bh[j]);
#pragma unroll
            for (int j = 0; j < 8; j++) mma16816(oacc[j], pa_h[sp], bl[j]);
        }
        __syncthreads();
    }

    // Epilogue: hi-only O (feeds the 2-term O projection).
    size_t row0 = (size_t)n * SEQ + q0 + wm + g;
    int colb = h * HDIM;
    float inv0 = 1.0f / l0, inv1 = 1.0f / l1;
#pragma unroll
    for (int nf = 0; nf < 8; nf++) {
        int cc = colb + 8 * nf + 2 * tg;
        __half h0 = __float2half_rn(oacc[nf][0] * inv0);
        __half h1 = __float2half_rn(oacc[nf][1] * inv0);
        __half h2 = __float2half_rn(oacc[nf][2] * inv1);
        __half h3 = __float2half_rn(oacc[nf][3] * inv1);
        *(uint32_t*)(g_ahi + row0 * EMBED + cc)       = h2pack(h0,h1);
        *(uint32_t*)(g_ahi + (row0 + 8) * EMBED + cc) = h2pack(h2,h3);
    }
}

// ---------------------------------------------------------------------------
// Launch
// ---------------------------------------------------------------------------
extern "C" void kernel_launch(void* const* d_in, const int* in_sizes, int n_in,
                              void* d_out, int out_size)
{
    const float* values  = (const float*)d_in[0];
    const float* keys    = (const float*)d_in[1];
    const float* queries = (const float*)d_in[2];
    const float* W_v = (const float*)d_in[3];
    const float* b_v = (const float*)d_in[4];
    const float* W_k = (const float*)d_in[5];
    const float* b_k = (const float*)d_in[6];
    const float* W_q = (const float*)d_in[7];
    const float* b_q = (const float*)d_in[8];
    const float* W_o = (const float*)d_in[9];
    const float* b_o = (const float*)d_in[10];
    float* out = (float*)d_out;

    cudaFuncSetAttribute(flash16_kernel,
                         cudaFuncAttributeMaxDynamicSharedMemorySize, FLASH16_SMEM);
    cudaFuncSetAttribute(gemm16_kernel,
                         cudaFuncAttributeMaxDynamicSharedMemorySize, GEMM16_SMEM);

    // Batched operand splits.
    splitw_kernel<<<dim3(ESQ / 4096, 4), 256>>>(W_v, W_k, W_q, W_o);
    splitx_kernel<<<dim3(XSZ / 4096, 3), 256>>>(values, keys, queries);

    // Fused Q/K/V projections (2-term).
    gemm16_kernel<<<dim3(EMBED / 128, NROWS / 128, 3), 128, GEMM16_SMEM>>>(
        b_q, b_k, b_v, nullptr, 0);

    // V transpose/split + flash.
    splitvt_kernel<<<dim3(SEQ / 64, HEADS, NBATCH), 256>>>();
    flash16_kernel<<<dim3(SEQ / 64, HEADS, NBATCH), 128, FLASH16_SMEM>>>();

    // Output projection (2-term).
    gemm16_kernel<<<dim3(EMBED / 128, NROWS / 128, 1), 128, GEMM16_SMEM>>>(
        b_o, nullptr, nullptr, out, 1);
}

// round 17
// speedup vs baseline: 1.8293x; 1.0870x over previous
#include <cuda_runtime.h>
#include <cuda_fp16.h>
#include <cstdint>

#define EMBED  1024
#define HEADS  16
#define HDIM   64
#define NBATCH 2
#define SEQ    2048
#define NROWS  (NBATCH * SEQ)   // 4096
#define ESQ    (EMBED * EMBED)
#define XSZ    (NROWS * EMBED)

// Scratch (no allocation allowed).
__device__ float  g_q[XSZ];
__device__ float  g_v[XSZ];
__device__ __half g_khi[XSZ];
__device__ __half g_vthi[NBATCH * HEADS * HDIM * SEQ];
__device__ __half g_vtlo[NBATCH * HEADS * HDIM * SEQ];
// Input splits (hi only): slots 0=values, 1=keys, 2=queries.
__device__ __half g_xhi[3 * XSZ];
// Weight splits: slots 0=W_v, 1=W_k, 2=W_q, 3=W_o.
__device__ __half g_whi[4 * ESQ];
__device__ __half g_wlo[4 * ESQ];
// Flash output (hi only; A operand of the O projection).
__device__ __half g_ahi[XSZ];

#define CP_ASYNC16(dst_u32, src_ptr) \
    asm volatile("cp.async.cg.shared.global [%0], [%1], 16;" :: "r"(dst_u32), "l"(src_ptr))

__device__ __forceinline__ void split2(float x, __half& hi, __half& lo) {
    hi = __float2half_rn(x);
    lo = __float2half_rn(x - __half2float(hi));
}
__device__ __forceinline__ uint32_t h2pack(__half a, __half b) {
    __half2 h = __halves2half2(a, b);
    return *(uint32_t*)&h;
}
__device__ __forceinline__ void mma16816(float* c, const uint32_t* a, const uint32_t* b) {
    asm volatile(
        "mma.sync.aligned.m16n8k16.row.col.f32.f16.f16.f32 "
        "{%0,%1,%2,%3}, {%4,%5,%6,%7}, {%8,%9}, {%0,%1,%2,%3};"
        : "+f"(c[0]), "+f"(c[1]), "+f"(c[2]), "+f"(c[3])
        : "r"(a[0]), "r"(a[1]), "r"(a[2]), "r"(a[3]), "r"(b[0]), "r"(b[1]));
}
__device__ __forceinline__ void ldsm_x4(uint32_t& r0, uint32_t& r1,
                                        uint32_t& r2, uint32_t& r3, uint32_t addr) {
    asm volatile("ldmatrix.sync.aligned.m8n8.x4.shared.b16 {%0,%1,%2,%3}, [%4];"
                 : "=r"(r0), "=r"(r1), "=r"(r2), "=r"(r3) : "r"(addr));
}
__device__ __forceinline__ uint32_t packf2(float x, float y) {
    __half2 h = __floats2half2_rn(x, y);
    return *(uint32_t*)&h;
}
__device__ __forceinline__ uint32_t packlo(float x, float y, uint32_t hi) {
    __half2 h = *(__half2*)&hi;
    return packf2(x - __low2float(h), y - __high2float(h));
}

// ---------------------------------------------------------------------------
// Batched splits, 4x float4 per thread (MLP=4).
// ---------------------------------------------------------------------------
__global__ __launch_bounds__(256) void splitx_kernel(
    const float* __restrict__ values, const float* __restrict__ keys,
    const float* __restrict__ queries)
{
    const int slot = blockIdx.y;
    const float* src = (slot == 0) ? values : (slot == 1) ? keys : queries;
    __half* hi = g_xhi + (size_t)slot * XSZ;
    size_t base = (size_t)blockIdx.x * 4096 + threadIdx.x * 4;
    float4 x[4];
#pragma unroll
    for (int j = 0; j < 4; j++) x[j] = *(const float4*)(src + base + j * 1024);
#pragma unroll
    for (int j = 0; j < 4; j++) {
        size_t i = base + j * 1024;
        __half h0 = __float2half_rn(x[j].x), h1 = __float2half_rn(x[j].y);
        __half h2 = __float2half_rn(x[j].z), h3 = __float2half_rn(x[j].w);
        *(uint2*)(hi + i) = make_uint2(h2pack(h0,h1), h2pack(h2,h3));
    }
}

__global__ __launch_bounds__(256) void splitw_kernel(
    const float* __restrict__ Wv, const float* __restrict__ Wk,
    const float* __restrict__ Wq, const float* __restrict__ Wo)
{
    const int slot = blockIdx.y;
    const float* src = (slot == 0) ? Wv : (slot == 1) ? Wk : (slot == 2) ? Wq : Wo;
    __half* hi = g_whi + (size_t)slot * ESQ;
    __half* lo = g_wlo + (size_t)slot * ESQ;
    size_t base = (size_t)blockIdx.x * 4096 + threadIdx.x * 4;
    float4 x[4];
#pragma unroll
    for (int j = 0; j < 4; j++) x[j] = *(const float4*)(src + base + j * 1024);
#pragma unroll
    for (int j = 0; j < 4; j++) {
        size_t i = base + j * 1024;
        __half h0,l0,h1,l1,h2,l2,h3,l3;
        split2(x[j].x,h0,l0); split2(x[j].y,h1,l1);
        split2(x[j].z,h2,l2); split2(x[j].w,h3,l3);
        *(uint2*)(hi + i) = make_uint2(h2pack(h0,h1), h2pack(h2,h3));
        *(uint2*)(lo + i) = make_uint2(h2pack(l0,l1), h2pack(l2,l3));
    }
}

// ---------------------------------------------------------------------------
// fp16 2-term GEMM (NT): out = A_hi*(W_hi + W_lo) + b. (proven R15)
// K projection (z==1) writes hi only (flash QK drops K_lo).
// ---------------------------------------------------------------------------
#define GARR   (128 * 32)
#define GSTAGE (3 * GARR)
#define GEMM16_SMEM (2 * GSTAGE * 2)  // 49152

__device__ __forceinline__ int gswz(int r, int kc) {
    int sr = r >> 1;
    int c  = ((r & 1) << 5) | kc;
    return sr * 64 + ((((c >> 3) ^ (sr & 7)) << 3) | (c & 7));
}

__global__ __launch_bounds__(128) void gemm16_kernel(
    const float* __restrict__ bq, const float* __restrict__ bk,
    const float* __restrict__ bv, float* __restrict__ out_ext, int mode)
{
    extern __shared__ __half gsm[];
    const int z = (mode == 0) ? (int)blockIdx.z : 3;   // 0=Q 1=K 2=V 3=O
    const int wslot = (z == 0) ? 2 : (z == 1) ? 1 : (z == 2) ? 0 : 3;

    const __half* Ahi_g;
    const float* bias;
    if (z < 3) {
        const int xslot = (z == 0) ? 2 : (z == 1) ? 1 : 0;
        Ahi_g = g_xhi + (size_t)xslot * XSZ;
        bias  = (z == 0) ? bq : (z == 1) ? bk : bv;
    } else {
        Ahi_g = g_ahi;
        bias  = bq;              // O launch passes b_o here
    }
    const __half* Bhi_g = g_whi + (size_t)wslot * ESQ;
    const __half* Blo_g = g_wlo + (size_t)wslot * ESQ;

    const int t    = threadIdx.x;
    const int lane = t & 31;
    const int wid  = t >> 5;
    const int g    = lane >> 2;
    const int tg   = lane & 3;
    const int sub  = lane >> 3;
    const int lr   = lane & 7;
    const int wm   = (wid & 1) * 64;
    const int wn   = (wid >> 1) * 64;
    const int c0 = blockIdx.x * 128;
    const int r0 = blockIdx.y * 128;

    const uint32_t smem_u32 = (uint32_t)__cvta_generic_to_shared(gsm);

    float acc[4][8][4];
#pragma unroll
    for (int mi = 0; mi < 4; mi++)
#pragma unroll
        for (int ni = 0; ni < 8; ni++)
#pragma unroll
            for (int e = 0; e < 4; e++) acc[mi][ni][e] = 0.f;

    auto issue = [&](int buf, int k0) {
#pragma unroll
        for (int i = 0; i < 4; i++) {
            int gid = t + i * 128;
            int row = gid >> 2;
            int ch  = gid & 3;
            uint32_t dst = smem_u32 + (uint32_t)(buf * GSTAGE + gswz(row, ch * 8)) * 2;
            size_t aoff = (size_t)(r0 + row) * EMBED + k0 + ch * 8;
            size_t boff = (size_t)(c0 + row) * EMBED + k0 + ch * 8;
            CP_ASYNC16(dst,                Ahi_g + aoff);
            CP_ASYNC16(dst + GARR * 2,     Bhi_g + boff);
            CP_ASYNC16(dst + 2 * GARR * 2, Blo_g + boff);
        }
        asm volatile("cp.async.commit_group;");
    };

    issue(0, 0);

    const int NT = EMBED / 32;
    for (int it = 0; it < NT; it++) {
        if (it + 1 < NT) {
            issue((it + 1) & 1, (it + 1) * 32);
            asm volatile("cp.async.wait_group 1;");
        } else {
            asm volatile("cp.async.wait_group 0;");
        }
        __syncthreads();

        const uint32_t base = (uint32_t)((it & 1) * GSTAGE);
        const uint32_t aho = base;
        const uint32_t bho = base + GARR, blo_ = base + 2 * GARR;

#pragma unroll
        for (int ks = 0; ks < 2; ks++) {
            const int kc0 = ks * 16;
            uint32_t bh[8][2], bl[8][2];
#pragma unroll
            for (int fp = 0; fp < 4; fp++) {
                int row = wn + 8 * (2 * fp + (sub >> 1)) + lr;
                int ch  = kc0 + (sub & 1) * 8;
                uint32_t off = (uint32_t)gswz(row, ch);
                ldsm_x4(bh[2*fp][0], bh[2*fp][1], bh[2*fp+1][0], bh[2*fp+1][1],
                        smem_u32 + (bho + off) * 2);
                ldsm_x4(bl[2*fp][0], bl[2*fp][1], bl[2*fp+1][0], bl[2*fp+1][1],
                        smem_u32 + (blo_ + off) * 2);
            }
#pragma unroll
            for (int mi = 0; mi < 4; mi++) {
                int row = wm + mi * 16 + (sub & 1) * 8 + lr;
                int ch  = kc0 + (sub >> 1) * 8;
                uint32_t off = (uint32_t)gswz(row, ch);
                uint32_t ah[4];
                ldsm_x4(ah[0], ah[1], ah[2], ah[3], smem_u32 + (aho + off) * 2);
#pragma unroll
                for (int ni = 0; ni < 8; ni++) mma16816(acc[mi][ni], ah, bh[ni]);
#pragma unroll
                for (int ni = 0; ni < 8; ni++) mma16816(acc[mi][ni], ah, bl[ni]);
            }
        }
        __syncthreads();
    }

    if (z == 1) {
        // K projection: hi only (flash QK drops K_lo).
#pragma unroll
        for (int mi = 0; mi < 4; mi++) {
            int r = r0 + wm + mi * 16 + g;
#pragma unroll
            for (int ni = 0; ni < 8; ni++) {
                int cc = c0 + wn + ni * 8 + 2 * tg;
                float bx = bias[cc], by = bias[cc + 1];
                __half h0 = __float2half_rn(acc[mi][ni][0] + bx);
                __half h1 = __float2half_rn(acc[mi][ni][1] + by);
                __half h2 = __float2half_rn(acc[mi][ni][2] + bx);
                __half h3 = __float2half_rn(acc[mi][ni][3] + by);
                *(uint32_t*)(g_khi + (size_t)r * EMBED + cc)     = h2pack(h0,h1);
                *(uint32_t*)(g_khi + (size_t)(r+8) * EMBED + cc) = h2pack(h2,h3);
            }
        }
    } else {
        float* out = (z == 0) ? g_q : (z == 2) ? g_v : out_ext;
#pragma unroll
        for (int mi = 0; mi < 4; mi++) {
            int r = r0 + wm + mi * 16 + g;
#pragma unroll
            for (int ni = 0; ni < 8; ni++) {
                int cc = c0 + wn + ni * 8 + 2 * tg;
                float bx = bias[cc], by = bias[cc + 1];
                *(float2*)(out + (size_t)r * EMBED + cc) =
                    make_float2(acc[mi][ni][0] + bx, acc[mi][ni][1] + by);
                *(float2*)(out + (size_t)(r + 8) * EMBED + cc) =
                    make_float2(acc[mi][ni][2] + bx, acc[mi][ni][3] + by);
            }
        }
    }
}

// ---------------------------------------------------------------------------
// V transpose/split for flash.
// ---------------------------------------------------------------------------
__global__ __launch_bounds__(256) void splitvt_kernel() {
    __shared__ float tile[64][65];
    const int n = blockIdx.z, h = blockIdx.y, s0 = blockIdx.x * 64;
    const int t = threadIdx.x;
#pragma unroll
    for (int i = 0; i < 4; i++) {
        int fi = t + i * 256;
        int r  = fi >> 4;
        int c4 = fi & 15;
        float4 v = *(const float4*)(g_v + ((size_t)n * SEQ + s0 + r) * EMBED + h * HDIM + c4 * 4);
        tile[r][c4 * 4 + 0] = v.x; tile[r][c4 * 4 + 1] = v.y;
        tile[r][c4 * 4 + 2] = v.z; tile[r][c4 * 4 + 3] = v.w;
    }
    __syncthreads();
#pragma unroll
    for (int i = 0; i < 4; i++) {
        int fi = t + i * 256;
        int d   = fi >> 4;
        int sc4 = fi & 15;
        size_t base = ((size_t)(n * HEADS + h) * HDIM + d) * SEQ + s0 + sc4 * 4;
        __half hh[4], ll[4];
#pragma unroll
        for (int j = 0; j < 4; j++) split2(tile[sc4 * 4 + j][d], hh[j], ll[j]);
        *(uint2*)(g_vthi + base) = make_uint2(h2pack(hh[0], hh[1]), h2pack(hh[2], hh[3]));
        *(uint2*)(g_vtlo + base) = make_uint2(h2pack(ll[0], ll[1]), h2pack(ll[2], ll[3]));
    }
}

// ---------------------------------------------------------------------------
// Tensor-core flash attention: 64-row Q tiles, 4 warps.
// QK^T = (Q_hi + Q_lo) * K_hi  (2 MMA terms; K_lo dropped).
// PV   = P_hi * (V_hi + V_lo)  (2 MMA terms; P_lo dropped, validated).
// Stage: Khi, Vthi, Vtlo (24 KB/stage, 48 KB total).
// ---------------------------------------------------------------------------
#define FT  4096
#define FSTAGE (3 * FT)
#define FLASH16_SMEM (2 * FSTAGE * 2)   // 49152 B

__device__ __forceinline__ int swzh(int r, int c) {
    return (r << 6) + ((((c >> 3) ^ (r & 7)) << 3) | (c & 7));
}

__global__ __launch_bounds__(128) void flash16_kernel() {
    extern __shared__ __half fsm[];
    const int n  = blockIdx.z;
    const int h  = blockIdx.y;
    const int q0 = blockIdx.x * 64;
    const int t    = threadIdx.x;
    const int lane = t & 31;
    const int wid  = t >> 5;
    const int g    = lane >> 2;
    const int tg   = lane & 3;
    const int sub  = lane >> 3;
    const int lr   = lane & 7;
    const int wm   = wid * 16;

    const uint32_t smem_u32 = (uint32_t)__cvta_generic_to_shared(fsm);

    uint32_t qa_h[4][4], qa_l[4][4];
    {
        const float* Qg = g_q + ((size_t)n * SEQ + q0 + wm) * EMBED + h * HDIM;
#pragma unroll
        for (int s = 0; s < 4; s++) {
            int c0 = 16 * s + 2 * tg;
#pragma unroll
            for (int rr = 0; rr < 2; rr++) {
                int row = g + rr * 8;
                float2 q01 = *(const float2*)(Qg + (size_t)row * EMBED + c0);
                float2 q23 = *(const float2*)(Qg + (size_t)row * EMBED + c0 + 8);
                q01.x *= 0.125f; q01.y *= 0.125f;
                q23.x *= 0.125f; q23.y *= 0.125f;
                qa_h[s][rr]     = packf2(q01.x, q01.y);
                qa_l[s][rr]     = packlo(q01.x, q01.y, qa_h[s][rr]);
                qa_h[s][rr + 2] = packf2(q23.x, q23.y);
                qa_l[s][rr + 2] = packlo(q23.x, q23.y, qa_h[s][rr + 2]);
            }
        }
    }

    float oacc[8][4];
#pragma unroll
    for (int nf = 0; nf < 8; nf++)
#pragma unroll
        for (int e = 0; e < 4; e++) oacc[nf][e] = 0.f;
    float m0 = -1e30f, m1 = -1e30f, l0 = 0.f, l1 = 0.f;

    const __half* srcK_hi = g_khi + ((size_t)n * SEQ) * EMBED + h * HDIM;
    const __half* srcV_hi = g_vthi + (size_t)(n * HEADS + h) * HDIM * SEQ;
    const __half* srcV_lo = g_vtlo + (size_t)(n * HEADS + h) * HDIM * SEQ;

    auto issue = [&](int tileidx, int buf) {
        int s0 = tileidx * 64;
#pragma unroll
        for (int i = 0; i < 4; i++) {
            int gid = t + i * 128;
            int r = gid >> 3;
            int c = gid & 7;
            uint32_t dsth = (uint32_t)(buf * FSTAGE + r * 64 + ((c ^ (r & 7)) << 3));
            CP_ASYNC16(smem_u32 + (dsth) * 2,
                       srcK_hi + (size_t)(s0 + r) * EMBED + c * 8);
            CP_ASYNC16(smem_u32 + (dsth + FT) * 2,
                       srcV_hi + (size_t)r * SEQ + s0 + c * 8);
            CP_ASYNC16(smem_u32 + (dsth + 2 * FT) * 2,
                       srcV_lo + (size_t)r * SEQ + s0 + c * 8);
        }
        asm volatile("cp.async.commit_group;");
    };

    issue(0, 0);

    const int NT = SEQ / 64;
    for (int it = 0; it < NT; it++) {
        if (it + 1 < NT) {
            issue(it + 1, (it + 1) & 1);
            asm volatile("cp.async.wait_group 1;");
        } else {
            asm volatile("cp.async.wait_group 0;");
        }
        __syncthreads();

        const uint32_t kho  = (uint32_t)((it & 1) * FSTAGE);
        const uint32_t vho  = kho + FT;
        const uint32_t vlo_ = kho + 2 * FT;

        float sa[8][4];
#pragma unroll
        for (int nf = 0; nf < 8; nf++)
#pragma unroll
            for (int e = 0; e < 4; e++) sa[nf][e] = 0.f;

#pragma unroll
        for (int s = 0; s < 4; s++) {
            uint32_t bh[8][2];
#pragma unroll
            for (int fp = 0; fp < 4; fp++) {
                int row = 8 * (2 * fp + (sub >> 1)) + lr;
                int ch  = 16 * s + (sub & 1) * 8;
                uint32_t off = (uint32_t)swzh(row, ch);
                ldsm_x4(bh[2*fp][0], bh[2*fp][1], bh[2*fp+1][0], bh[2*fp+1][1],
                        smem_u32 + (kho + off) * 2);
            }
#pragma unroll
            for (int j = 0; j < 8; j++) mma16816(sa[j], qa_h[s], bh[j]);
#pragma unroll
            for (int j = 0; j < 8; j++) mma16816(sa[j], qa_l[s], bh[j]);
        }

        float mx0 = -1e30f, mx1 = -1e30f;
#pragma unroll
        for (int nf = 0; nf < 8; nf++) {
            mx0 = fmaxf(mx0, fmaxf(sa[nf][0], sa[nf][1]));
            mx1 = fmaxf(mx1, fmaxf(sa[nf][2], sa[nf][3]));
        }
        mx0 = fmaxf(mx0, __shfl_xor_sync(0xffffffffu, mx0, 1));
        mx0 = fmaxf(mx0, __shfl_xor_sync(0xffffffffu, mx0, 2));
        mx1 = fmaxf(mx1, __shfl_xor_sync(0xffffffffu, mx1, 1));
        mx1 = fmaxf(mx1, __shfl_xor_sync(0xffffffffu, mx1, 2));
        float mn0 = fmaxf(m0, mx0), mn1 = fmaxf(m1, mx1);
        float corr0 = __expf(m0 - mn0), corr1 = __expf(m1 - mn1);
        m0 = mn0; m1 = mn1;
        float rs0 = 0.f, rs1 = 0.f;
#pragma unroll
        for (int nf = 0; nf < 8; nf++) {
            sa[nf][0] = __expf(sa[nf][0] - mn0); rs0 += sa[nf][0];
            sa[nf][1] = __expf(sa[nf][1] - mn0); rs0 += sa[nf][1];
            sa[nf][2] = __expf(sa[nf][2] - mn1); rs1 += sa[nf][2];
            sa[nf][3] = __expf(sa[nf][3] - mn1); rs1 += sa[nf][3];
        }
        rs0 += __shfl_xor_sync(0xffffffffu, rs0, 1);
        rs0 += __shfl_xor_sync(0xffffffffu, rs0, 2);
        rs1 += __shfl_xor_sync(0xffffffffu, rs1, 1);
        rs1 += __shfl_xor_sync(0xffffffffu, rs1, 2);
        l0 = l0 * corr0 + rs0;
        l1 = l1 * corr1 + rs1;
#pragma unroll
        for (int nf = 0; nf < 8; nf++) {
            oacc[nf][0] *= corr0; oacc[nf][1] *= corr0;
            oacc[nf][2] *= corr1; oacc[nf][3] *= corr1;
        }

        uint32_t pa_h[4][4];
#pragma unroll
        for (int sp = 0; sp < 4; sp++) {
            pa_h[sp][0] = packf2(sa[2 * sp][0], sa[2 * sp][1]);
            pa_h[sp][1] = packf2(sa[2 * sp][2], sa[2 * sp][3]);
            pa_h[sp][2] = packf2(sa[2 * sp + 1][0], sa[2 * sp + 1][1]);
            pa_h[sp][3] = packf2(sa[2 * sp + 1][2], sa[2 * sp + 1][3]);
        }

#pragma unroll
        for (int sp = 0; sp < 4; sp++) {
            uint32_t bh[8][2], bl[8][2];
#pragma unroll
            for (int fp = 0; fp < 4; fp++) {
                int row = 8 * (2 * fp + (sub >> 1)) + lr;
                int ch  = 16 * sp + (sub & 1) * 8;
                uint32_t off = (uint32_t)swzh(row, ch);
                ldsm_x4(bh[2*fp][0], bh[2*fp][1], bh[2*fp+1][0], bh[2*fp+1][1],
                        smem_u32 + (vho + off) * 2);
                ldsm_x4(bl[2*fp][0], bl[2*fp][1], bl[2*fp+1][0], bl[2*fp+1][1],
                        smem_u32 + (vlo_ + off) * 2);
            }
#pragma unroll
            for (int j = 0; j < 8; j++) mma16816(oacc[j], pa_h[sp], bh[j]);
#pragma unroll
            for (int j = 0; j < 8; j++) mma16816(oacc[j], pa_h[sp], bl[j]);
        }
        __syncthreads();
    }

    // Epilogue: hi-only O (feeds the 2-term O projection).
    size_t row0 = (size_t)n * SEQ + q0 + wm + g;
    int colb = h * HDIM;
    float inv0 = 1.0f / l0, inv1 = 1.0f / l1;
#pragma unroll
    for (int nf = 0; nf < 8; nf++) {
        int cc = colb + 8 * nf + 2 * tg;
        __half h0 = __float2half_rn(oacc[nf][0] * inv0);
        __half h1 = __float2half_rn(oacc[nf][1] * inv0);
        __half h2 = __float2half_rn(oacc[nf][2] * inv1);
        __half h3 = __float2half_rn(oacc[nf][3] * inv1);
        *(uint32_t*)(g_ahi + row0 * EMBED + cc)       = h2pack(h0,h1);
        *(uint32_t*)(g_ahi + (row0 + 8) * EMBED + cc) = h2pack(h2,h3);
    }
}

// ---------------------------------------------------------------------------
// Launch
// ---------------------------------------------------------------------------
extern "C" void kernel_launch(void* const* d_in, const int* in_sizes, int n_in,
                              void* d_out, int out_size)
{
    const float* values  = (const float*)d_in[0];
    const float* keys    = (const float*)d_in[1];
    const float* queries = (const float*)d_in[2];
    const float* W_v = (const float*)d_in[3];
    const float* b_v = (const float*)d_in[4];
    const float* W_k = (const float*)d_in[5];
    const float* b_k = (const float*)d_in[6];
    const float* W_q = (const float*)d_in[7];
    const float* b_q = (const float*)d_in[8];
    const float* W_o = (const float*)d_in[9];
    const float* b_o = (const float*)d_in[10];
    float* out = (float*)d_out;

    cudaFuncSetAttribute(flash16_kernel,
                         cudaFuncAttributeMaxDynamicSharedMemorySize, FLASH16_SMEM);
    cudaFuncSetAttribute(gemm16_kernel,
                         cudaFuncAttributeMaxDynamicSharedMemorySize, GEMM16_SMEM);

    // Batched operand splits.
    splitw_kernel<<<dim3(ESQ / 4096, 4), 256>>>(W_v, W_k, W_q, W_o);
    splitx_kernel<<<dim3(XSZ / 4096, 3), 256>>>(values, keys, queries);

    // Fused Q/K/V projections (2-term).
    gemm16_kernel<<<dim3(EMBED / 128, NROWS / 128, 3), 128, GEMM16_SMEM>>>(
        b_q, b_k, b_v, nullptr, 0);

    // V transpose/split + flash (QK 2-term, PV 2-term).
    splitvt_kernel<<<dim3(SEQ / 64, HEADS, NBATCH), 256>>>();
    flash16_kernel<<<dim3(SEQ / 64, HEADS, NBATCH), 128, FLASH16_SMEM>>>();

    // Output projection (2-term).
    gemm16_kernel<<<dim3(EMBED / 128, NROWS / 128, 1), 128, GEMM16_SMEM>>>(
        b_o, nullptr, nullptr, out, 1);
}